// round 1
// baseline (speedup 1.0000x reference)
#include <cuda_runtime.h>
#include <cuda_bf16.h>

// out[b,d,n] = w[d] * in[b,d,n];  B=8, D=2048, N=2048, fp32.
// Pure streaming: 268 MB traffic, HBM-bound. float4 vectorized, exact-cover grid.

static constexpr int B = 8;
static constexpr int D = 2048;
static constexpr int N = 2048;
static constexpr long long TOTAL4 = (long long)B * D * N / 4;  // 8,388,608 float4s
static constexpr int N4 = N / 4;   // 512 float4 per channel row

__global__ void __launch_bounds__(256)
channel_scale_kernel(const float4* __restrict__ in,
                     const float*  __restrict__ w,
                     float4*       __restrict__ out)
{
    long long i = (long long)blockIdx.x * blockDim.x + threadIdx.x;
    if (i >= TOTAL4) return;
    // d = (i / N4) % D ; N4=512, D=2048 -> bit ops
    int d = (int)((i >> 9) & (D - 1));
    float s = __ldg(w + d);
    float4 v = in[i];
    v.x *= s; v.y *= s; v.z *= s; v.w *= s;
    out[i] = v;
}

extern "C" void kernel_launch(void* const* d_in, const int* in_sizes, int n_in,
                              void* d_out, int out_size)
{
    const float4* in = (const float4*)d_in[0];   // inputs [B, D, N] fp32
    const float*  w  = (const float*)d_in[1];    // attention_weights [D] fp32
    float4* out = (float4*)d_out;

    int threads = 256;
    long long blocks = (TOTAL4 + threads - 1) / threads;  // 32768
    channel_scale_kernel<<<(unsigned)blocks, threads>>>(in, w, out);
}

// round 2
// speedup vs baseline: 1.0177x; 1.0177x over previous
#include <cuda_runtime.h>
#include <cuda_bf16.h>

// out[b,d,n] = w[d] * in[b,d,n];  B=8, D=2048, N=2048, fp32.
// HBM-bound stream. Unroll 4 per thread with front-batched independent
// LDG.128s to raise per-warp MLP (R1: MLP=1 -> DRAM only 73%).

static constexpr int B = 8;
static constexpr int D = 2048;
static constexpr int N = 2048;
static constexpr long long TOTAL4 = (long long)B * D * N / 4;  // 8,388,608 float4
static constexpr int THREADS = 256;
static constexpr int UNROLL  = 4;
static constexpr int BLOCK_ELEMS = THREADS * UNROLL;           // 1024 float4 / block

__global__ void __launch_bounds__(THREADS)
channel_scale_kernel(const float4* __restrict__ in,
                     const float*  __restrict__ w,
                     float4*       __restrict__ out)
{
    long long base = (long long)blockIdx.x * BLOCK_ELEMS + threadIdx.x;

    // Front-batch all loads: 4 independent LDG.128 in flight per thread.
    float4 v[UNROLL];
#pragma unroll
    for (int k = 0; k < UNROLL; k++) {
        v[k] = in[base + (long long)k * THREADS];
    }

#pragma unroll
    for (int k = 0; k < UNROLL; k++) {
        long long i = base + (long long)k * THREADS;
        // channel index: i4 / (N/4) % D ; N/4 = 512, D = 2048
        int d = (int)((i >> 9) & (D - 1));
        float s = __ldg(w + d);          // L1/L2 resident (8 KB)
        v[k].x *= s; v[k].y *= s; v[k].z *= s; v[k].w *= s;
        out[i] = v[k];
    }
}

extern "C" void kernel_launch(void* const* d_in, const int* in_sizes, int n_in,
                              void* d_out, int out_size)
{
    const float4* in = (const float4*)d_in[0];   // inputs [B, D, N] fp32
    const float*  w  = (const float*)d_in[1];    // attention_weights [D] fp32
    float4* out = (float4*)d_out;

    long long blocks = TOTAL4 / BLOCK_ELEMS;     // 8192, exact cover
    channel_scale_kernel<<<(unsigned)blocks, THREADS>>>(in, w, out);
}